// round 11
// baseline (speedup 1.0000x reference)
#include <cuda_runtime.h>
#include <math.h>

// Problem constants
constexpr int kB = 256, kN = 1152, kD = 8, kO = 10, kE = 16;
constexpr int kOE = kO * kE;  // 160

// Tiling: block owns 8 n and a QUARTER of the batches (64), in 8 chunks of 8.
constexpr int kNL   = 8;
constexpr int kTH   = 320;        // tid = nl(b0-2) + eg(b3-4) + o(b5+)
constexpr int kGX   = kN / kNL;   // 144
constexpr int kGY   = 4;
constexpr int kBH   = kB / kGY;   // 64
constexpr int kCB   = 8;
constexpr int kNCH  = kBH / kCB;  // 8

// SMEM (floats)
constexpr int kUSd  = kBH;                      // 64
constexpr int kUSnl = kD * kUSd + 4;            // 516
constexpr int kOffV = kNL * kUSnl;              // 4128
constexpr int kVSo  = 32;                       // per-o: 16 e-values x 2 batch lanes
constexpr int kVSbp = kO * kVSo + 4;            // 324 (16B-multiple, pair stride)
constexpr int kOffL = kOffV + (kBH / 2) * kVSbp;   // 4128 + 10368 = 14496
constexpr int kLSbp = 20;
constexpr int kLSnl = (kBH / 2) * kLSbp + 4;       // 644 (mod 32 == 4)
constexpr int kSmemFloats1 = kOffL + kNL * kLSnl;  // 19648
constexpr int kSmemBytes1  = kSmemFloats1 * 4;     // 78592 (x2 CTA = 157KB)
constexpr int kSmemBytes0  = kOffV * 4;            // 16512

typedef unsigned long long u64;

__device__ float g_part[(size_t)kGX * kB * kOE];  // 23.6 MB
__device__ float g_vsum[kB * kOE];

#define FMA2(d, a, b_) asm("fma.rn.f32x2 %0, %1, %2, %0;" : "+l"(d) : "l"(a), "l"(b_))
#define MUL2(d, a, b_) asm("mul.rn.f32x2 %0, %1, %2;" : "=l"(d) : "l"(a), "l"(b_))
#define ADD2(d, a, b_) asm("add.rn.f32x2 %0, %1, %2;" : "=l"(d) : "l"(a), "l"(b_))
#define PACK2(d, lo, hi) \
  asm("mov.b64 %0, {%1, %2};" : "=l"(d) : "r"(__float_as_uint(lo)), "r"(__float_as_uint(hi)))
#define UNPK2(lo, hi, v)                                                \
  do {                                                                  \
    unsigned _l, _h;                                                    \
    asm("mov.b64 {%0, %1}, %2;" : "=r"(_l), "=r"(_h) : "l"(v));         \
    lo = __uint_as_float(_l); hi = __uint_as_float(_h);                 \
  } while (0)

__global__ void noop_kernel() {}

// 4x4 u_ji tile (bias included) for one chunk of 8 batches.
__device__ __forceinline__ void compute_acc(
    u64 acc[4][4], const float* __restrict__ up, const float w[kD][4], u64 bp)
{
#pragma unroll
  for (int k = 0; k < 4; k++)
#pragma unroll
    for (int j = 0; j < 4; j++) acc[k][j] = bp;
#pragma unroll
  for (int d = 0; d < kD; d++) {
    ulonglong2 ua = *(const ulonglong2*)(up + d * kUSd);      // b (0,1),(2,3)
    ulonglong2 ub = *(const ulonglong2*)(up + d * kUSd + 4);  // b (4,5),(6,7)
    u64 w2[4];
    PACK2(w2[0], w[d][0], w[d][0]); PACK2(w2[1], w[d][1], w[d][1]);
    PACK2(w2[2], w[d][2], w[d][2]); PACK2(w2[3], w[d][3], w[d][3]);
    FMA2(acc[0][0], ua.x, w2[0]); FMA2(acc[0][1], ua.x, w2[1]);
    FMA2(acc[0][2], ua.x, w2[2]); FMA2(acc[0][3], ua.x, w2[3]);
    FMA2(acc[1][0], ua.y, w2[0]); FMA2(acc[1][1], ua.y, w2[1]);
    FMA2(acc[1][2], ua.y, w2[2]); FMA2(acc[1][3], ua.y, w2[3]);
    FMA2(acc[2][0], ub.x, w2[0]); FMA2(acc[2][1], ub.x, w2[1]);
    FMA2(acc[2][2], ub.x, w2[2]); FMA2(acc[2][3], ub.x, w2[3]);
    FMA2(acc[3][0], ub.y, w2[0]); FMA2(acc[3][1], ub.y, w2[1]);
    FMA2(acc[3][2], ub.y, w2[2]); FMA2(acc[3][3], ub.y, w2[3]);
  }
}

// MODE 0: c uniform (0.1 folded into squash).  MODE 1: c = softmax_o(<u_ji, g_vsum>).
template <int MODE>
__global__ void __launch_bounds__(kTH, 2) pass_kernel(
    const float* __restrict__ u_i,
    const float* __restrict__ W,
    const float* __restrict__ bias)
{
  extern __shared__ float sm[];
  float* u_s = sm;              // [nl(516)][d(64)][b]
  float* v_s = sm + kOffV;      // [b-pair(324)][o(32)][e*2 + (b&1)]  pair-packed
  float* l_s = sm + kOffL;      // [nl(644)][b-pair(20)][o*2] logits -> c, pair-packed

  const int tid = threadIdx.x;
  const int nl  = tid & 7;
  const int eg  = (tid >> 3) & 3;
  const int o   = tid >> 5;
  const int n0  = blockIdx.x * kNL;
  const int bb0 = blockIdx.y * kBH;

  // ---- W slice + bias (scalars; packed per chunk) ----
  float w[kD][4];
  {
    const float* Wp = W + ((size_t)(n0 + nl) * kO + o) * (kD * kE) + eg * 4;
#pragma unroll
    for (int d = 0; d < kD; d++) {
      float4 w4 = *(const float4*)(Wp + d * kE);
      w[d][0] = w4.x; w[d][1] = w4.y; w[d][2] = w4.z; w[d][3] = w4.w;
    }
  }
  const float bv = bias[(n0 + nl) * kO + o];
  u64 bp; PACK2(bp, bv, bv);

  // ---- stage u: [b][n][d] -> [nl][d][b_local] ----
  for (int i = tid; i < kBH * kNL * 2; i += kTH) {
    int b = i >> 4, nl2 = (i >> 1) & 7, h = i & 1;
    float4 t = *(const float4*)(u_i + ((size_t)(bb0 + b) * kN + n0 + nl2) * kD + h * 4);
    float* du = u_s + nl2 * kUSnl + h * 4 * kUSd + b;
    du[0] = t.x; du[kUSd] = t.y; du[2 * kUSd] = t.z; du[3 * kUSd] = t.w;
  }
  // ---- stage v pair-packed (MODE 1): v_s[bp][o][e*2+(b&1)] ----
  if (MODE) {
    for (int i = tid; i < kBH * (kOE / 4); i += kTH) {  // 2560
      int b = i / 40, q = i - b * 40;
      int oo = q >> 2, e0 = (q & 3) * 4;
      float4 t = *(const float4*)(g_vsum + (size_t)(bb0 + b) * kOE + oo * kE + e0);
      float* dv = v_s + (b >> 1) * kVSbp + oo * kVSo + e0 * 2 + (b & 1);
      dv[0] = t.x; dv[2] = t.y; dv[4] = t.z; dv[6] = t.w;
    }
  }
  __syncthreads();

  const float* up_base = u_s + nl * kUSnl;
  const int mm = ((nl >> 2) & 1) * 8 + ((nl >> 1) & 1) * 4 + (nl & 1) * 2;
  const int kk = mm >> 2, j0 = mm & 3;

  if (MODE) {
    // ===== Phase A: logits for all chunks (no barriers inside) =====
    for (int ch = 0; ch < kNCH; ch++) {
      const int bc  = ch * kCB;
      const int bc2 = ch * 4;  // b-pair base
      u64 acc[4][4];
      compute_acc(acc, up_base + bc, w, bp);

      u64 ag[4] = {0ull, 0ull, 0ull, 0ull};
#pragma unroll
      for (int k = 0; k < 4; k++) {
        const float* vp = v_s + (bc2 + k) * kVSbp + o * kVSo + eg * 8;
        ulonglong2 va = *(const ulonglong2*)vp;       // e pairs e0, e0+1
        ulonglong2 vb = *(const ulonglong2*)(vp + 4); // e pairs e0+2, e0+3
        FMA2(ag[k], acc[k][0], va.x);
        FMA2(ag[k], acc[k][1], va.y);
        FMA2(ag[k], acc[k][2], vb.x);
        FMA2(ag[k], acc[k][3], vb.y);
      }
      // eg-reduction on packed u64 (lane bits 3,4)
#pragma unroll
      for (int k = 0; k < 4; k++) {
        u64 r = __shfl_xor_sync(0xffffffffu, ag[k], 8);
        ADD2(ag[k], ag[k], r);
        r = __shfl_xor_sync(0xffffffffu, ag[k], 16);
        ADD2(ag[k], ag[k], r);
      }
      if (eg == 0) {
        float* ar = l_s + nl * kLSnl + bc2 * kLSbp + o * 2;
#pragma unroll
        for (int k = 0; k < 4; k++)
          *(u64*)(ar + k * kLSbp) = ag[k];
      }
    }
    __syncthreads();

    // ===== Phase B: softmax over o per (nl, b-pair); c stays pair-packed =====
    for (int i = tid; i < kNL * (kBH / 2); i += kTH) {  // 256 pair-rows
      float* row = l_s + (i >> 5) * kLSnl + (i & 31) * kLSbp;
      float ax[kO], ay[kO];
      float sx = 0.f, sy = 0.f;
#pragma unroll
      for (int q = 0; q < kO; q++) {
        float2 t = *(const float2*)(row + q * 2);
        ax[q] = __expf(t.x); ay[q] = __expf(t.y);
        sx += ax[q]; sy += ay[q];
      }
      float ix = 1.f / sx, iy = 1.f / sy;
#pragma unroll
      for (int q = 0; q < kO; q++)
        *(float2*)(row + q * 2) = make_float2(ax[q] * ix, ay[q] * iy);
    }
    __syncthreads();
  }

  // ===== Phase C: weighted sum, nl reduce-scatter, store partials =====
  for (int ch = 0; ch < kNCH; ch++) {
    const int bc  = ch * kCB;
    const int bc2 = ch * 4;
    const int bca = bb0 + bc;
    u64 acc[4][4];
    compute_acc(acc, up_base + bc, w, bp);

    u64 v16[16];
    if (MODE) {
      const float* cp = l_s + nl * kLSnl + bc2 * kLSbp + o * 2;
#pragma unroll
      for (int k = 0; k < 4; k++) {
        u64 c2 = *(const u64*)(cp + k * kLSbp);  // (c[b even], c[b odd])
#pragma unroll
        for (int j = 0; j < 4; j++) MUL2(v16[k * 4 + j], acc[k][j], c2);
      }
    } else {
#pragma unroll
      for (int k = 0; k < 4; k++)
#pragma unroll
        for (int j = 0; j < 4; j++) v16[k * 4 + j] = acc[k][j];
    }

    // reduce-scatter over nl (lane bits 0-2): 3 levels
    u64 v8[8];
    {
      const bool sel = (nl >> 2) & 1;
#pragma unroll
      for (int i = 0; i < 8; i++) {
        u64 send = sel ? v16[i] : v16[8 + i];
        u64 recv = __shfl_xor_sync(0xffffffffu, send, 4);
        u64 keep = sel ? v16[8 + i] : v16[i];
        ADD2(v8[i], keep, recv);
      }
    }
    u64 v4[4];
    {
      const bool sel = (nl >> 1) & 1;
#pragma unroll
      for (int i = 0; i < 4; i++) {
        u64 send = sel ? v8[i] : v8[4 + i];
        u64 recv = __shfl_xor_sync(0xffffffffu, send, 2);
        u64 keep = sel ? v8[4 + i] : v8[i];
        ADD2(v4[i], keep, recv);
      }
    }
    u64 v2[2];
    {
      const bool sel = nl & 1;
#pragma unroll
      for (int i = 0; i < 2; i++) {
        u64 send = sel ? v4[i] : v4[2 + i];
        u64 recv = __shfl_xor_sync(0xffffffffu, send, 1);
        u64 keep = sel ? v4[2 + i] : v4[i];
        ADD2(v2[i], keep, recv);
      }
    }
    {
      float l0, h0, l1, h1;
      UNPK2(l0, h0, v2[0]); UNPK2(l1, h1, v2[1]);
      float* dp = &g_part[((size_t)blockIdx.x * kB + bca + 2 * kk) * kOE
                          + o * kE + eg * 4 + j0];
      *(float2*)dp         = make_float2(l0, l1);
      *(float2*)(dp + kOE) = make_float2(h0, h1);
    }
  }
}

// Reduce 144 partials (scaled) + squash; mode 0: vsum=v, 1: vsum+=v, 2: out=v.
__global__ void squash_kernel(float* __restrict__ out, int mode, float scale) {
  int gt = blockIdx.x * blockDim.x + threadIdx.x;
  if (gt >= kB * kO * 4) return;
  int eq = gt & 3, row = gt >> 2;
  const float* pp = g_part + (size_t)row * kE + eq * 4;
  float4 a = {0.f, 0.f, 0.f, 0.f};
#pragma unroll 4
  for (int p = 0; p < kGX; p++) {
    float4 t = *(const float4*)(pp + (size_t)p * kB * kOE);
    a.x += t.x; a.y += t.y; a.z += t.z; a.w += t.w;
  }
  a.x *= scale; a.y *= scale; a.z *= scale; a.w *= scale;
  float n2 = a.x * a.x + a.y * a.y + a.z * a.z + a.w * a.w;
  n2 += __shfl_xor_sync(0xffffffffu, n2, 1);
  n2 += __shfl_xor_sync(0xffffffffu, n2, 2);
  float f = sqrtf(n2) / (1.f + n2);
  float4 v = make_float4(a.x * f, a.y * f, a.z * f, a.w * f);
  if (mode == 2) {
    *(float4*)(out + (size_t)row * kE + eq * 4) = v;
  } else if (mode == 1) {
    float4 old = *(const float4*)(g_vsum + (size_t)row * kE + eq * 4);
    v.x += old.x; v.y += old.y; v.z += old.z; v.w += old.w;
    *(float4*)(g_vsum + (size_t)row * kE + eq * 4) = v;
  } else {
    *(float4*)(g_vsum + (size_t)row * kE + eq * 4) = v;
  }
}

extern "C" void kernel_launch(void* const* d_in, const int* in_sizes, int n_in,
                              void* d_out, int out_size) {
  const float* u    = (const float*)d_in[0];
  const float* W    = (const float*)d_in[1];
  const float* bias = (const float*)d_in[2];
  float* out = (float*)d_out;

  cudaFuncSetAttribute((const void*)pass_kernel<0>,
                       cudaFuncAttributeMaxDynamicSharedMemorySize, kSmemBytes0);
  cudaFuncSetAttribute((const void*)pass_kernel<1>,
                       cudaFuncAttributeMaxDynamicSharedMemorySize, kSmemBytes1);

  dim3 grid(kGX, kGY);  // 576 blocks, 2 CTAs/SM

  noop_kernel<<<1, 32>>>();  // keeps ncu -s 5 -c 1 on the 2nd pass_kernel<1>

  pass_kernel<0><<<grid, kTH, kSmemBytes0>>>(u, W, bias);
  squash_kernel<<<40, 256>>>(nullptr, 0, 0.1f);

  pass_kernel<1><<<grid, kTH, kSmemBytes1>>>(u, W, bias);
  squash_kernel<<<40, 256>>>(nullptr, 1, 1.0f);

  pass_kernel<1><<<grid, kTH, kSmemBytes1>>>(u, W, bias);
  squash_kernel<<<40, 256>>>(out, 2, 1.0f);
}

// round 12
// speedup vs baseline: 1.2189x; 1.2189x over previous
#include <cuda_runtime.h>
#include <math.h>

// Problem constants
constexpr int kB = 256, kN = 1152, kD = 8, kO = 10, kE = 16;
constexpr int kOE = kO * kE;  // 160

// Tiling: block owns 8 n and a QUARTER of the batches (64), in 8 chunks of 8.
constexpr int kNL   = 8;
constexpr int kTH   = 320;        // tid = nl(b0-2) + eg(b3-4) + o(b5+)
constexpr int kGX   = kN / kNL;   // 144
constexpr int kGY   = 4;
constexpr int kBH   = kB / kGY;   // 64
constexpr int kCB   = 8;
constexpr int kNCH  = kBH / kCB;  // 8

// SMEM (floats)
constexpr int kUSd  = kBH;                      // 64
constexpr int kUSnl = kD * kUSd + 4;            // 516
constexpr int kOffV = kNL * kUSnl;              // 4128
constexpr int kVSo  = 32;                       // per-o: 16 e x 2 batch lanes
constexpr int kVSbp = kO * kVSo + 4;            // 324
constexpr int kOffL = kOffV + (kBH / 2) * kVSbp;   // 14496
constexpr int kLSbp = 20;
constexpr int kLSnl = (kBH / 2) * kLSbp + 4;       // 644 (mod 32 == 4)
constexpr int kSmemFloats1 = kOffL + kNL * kLSnl;  // 19648
constexpr int kSmemBytes1  = kSmemFloats1 * 4;     // 78592 (x2 CTA = 157KB)
constexpr int kSmemBytes0  = kOffV * 4;            // 16512

typedef unsigned long long u64;

__device__ float g_part[(size_t)kGX * kB * kOE];  // 23.6 MB
__device__ float g_vsum[kB * kOE];

#define FMA2(d, a, b_) asm("fma.rn.f32x2 %0, %1, %2, %0;" : "+l"(d) : "l"(a), "l"(b_))
#define MUL2(d, a, b_) asm("mul.rn.f32x2 %0, %1, %2;" : "=l"(d) : "l"(a), "l"(b_))
#define ADD2(d, a, b_) asm("add.rn.f32x2 %0, %1, %2;" : "=l"(d) : "l"(a), "l"(b_))
#define PACK2(d, lo, hi) \
  asm("mov.b64 %0, {%1, %2};" : "=l"(d) : "r"(__float_as_uint(lo)), "r"(__float_as_uint(hi)))
#define UNPK2(lo, hi, v)                                                \
  do {                                                                  \
    unsigned _l, _h;                                                    \
    asm("mov.b64 {%0, %1}, %2;" : "=r"(_l), "=r"(_h) : "l"(v));         \
    lo = __uint_as_float(_l); hi = __uint_as_float(_h);                 \
  } while (0)

__global__ void noop_kernel() {}

// 4x4 u_ji tile (bias included) for one chunk of 8 batches.
__device__ __forceinline__ void compute_acc(
    u64 acc[4][4], const float* __restrict__ up, const float w[kD][4], u64 bp)
{
#pragma unroll
  for (int k = 0; k < 4; k++)
#pragma unroll
    for (int j = 0; j < 4; j++) acc[k][j] = bp;
#pragma unroll
  for (int d = 0; d < kD; d++) {
    ulonglong2 ua = *(const ulonglong2*)(up + d * kUSd);      // b (0,1),(2,3)
    ulonglong2 ub = *(const ulonglong2*)(up + d * kUSd + 4);  // b (4,5),(6,7)
    u64 w2[4];
    PACK2(w2[0], w[d][0], w[d][0]); PACK2(w2[1], w[d][1], w[d][1]);
    PACK2(w2[2], w[d][2], w[d][2]); PACK2(w2[3], w[d][3], w[d][3]);
    FMA2(acc[0][0], ua.x, w2[0]); FMA2(acc[0][1], ua.x, w2[1]);
    FMA2(acc[0][2], ua.x, w2[2]); FMA2(acc[0][3], ua.x, w2[3]);
    FMA2(acc[1][0], ua.y, w2[0]); FMA2(acc[1][1], ua.y, w2[1]);
    FMA2(acc[1][2], ua.y, w2[2]); FMA2(acc[1][3], ua.y, w2[3]);
    FMA2(acc[2][0], ub.x, w2[0]); FMA2(acc[2][1], ub.x, w2[1]);
    FMA2(acc[2][2], ub.x, w2[2]); FMA2(acc[2][3], ub.x, w2[3]);
    FMA2(acc[3][0], ub.y, w2[0]); FMA2(acc[3][1], ub.y, w2[1]);
    FMA2(acc[3][2], ub.y, w2[2]); FMA2(acc[3][3], ub.y, w2[3]);
  }
}

// MODE 0: c uniform (0.1 folded into squash).  MODE 1: c = softmax_o(<u_ji, g_vsum>).
// acc computed ONCE per chunk and reused across the softmax barriers.
template <int MODE>
__global__ void __launch_bounds__(kTH, 2) pass_kernel(
    const float* __restrict__ u_i,
    const float* __restrict__ W,
    const float* __restrict__ bias)
{
  extern __shared__ float sm[];
  float* u_s = sm;              // [nl(516)][d(64)][b]
  float* v_s = sm + kOffV;      // [b-pair(324)][o(32)][e*2 + (b&1)]
  float* l_s = sm + kOffL;      // [nl(644)][b-pair(20)][o*2] logits -> c

  const int tid = threadIdx.x;
  const int nl  = tid & 7;
  const int eg  = (tid >> 3) & 3;
  const int o   = tid >> 5;
  const int n0  = blockIdx.x * kNL;
  const int bb0 = blockIdx.y * kBH;

  // ---- W slice + bias ----
  float w[kD][4];
  {
    const float* Wp = W + ((size_t)(n0 + nl) * kO + o) * (kD * kE) + eg * 4;
#pragma unroll
    for (int d = 0; d < kD; d++) {
      float4 w4 = *(const float4*)(Wp + d * kE);
      w[d][0] = w4.x; w[d][1] = w4.y; w[d][2] = w4.z; w[d][3] = w4.w;
    }
  }
  const float bv = bias[(n0 + nl) * kO + o];
  u64 bp; PACK2(bp, bv, bv);

  // ---- stage u: [b][n][d] -> [nl][d][b_local] ----
  for (int i = tid; i < kBH * kNL * 2; i += kTH) {
    int b = i >> 4, nl2 = (i >> 1) & 7, h = i & 1;
    float4 t = *(const float4*)(u_i + ((size_t)(bb0 + b) * kN + n0 + nl2) * kD + h * 4);
    float* du = u_s + nl2 * kUSnl + h * 4 * kUSd + b;
    du[0] = t.x; du[kUSd] = t.y; du[2 * kUSd] = t.z; du[3 * kUSd] = t.w;
  }
  // ---- stage v pair-packed (MODE 1) ----
  if (MODE) {
    for (int i = tid; i < kBH * (kOE / 4); i += kTH) {  // 2560
      int b = i / 40, q = i - b * 40;
      int oo = q >> 2, e0 = (q & 3) * 4;
      float4 t = *(const float4*)(g_vsum + (size_t)(bb0 + b) * kOE + oo * kE + e0);
      float* dv = v_s + (b >> 1) * kVSbp + oo * kVSo + e0 * 2 + (b & 1);
      dv[0] = t.x; dv[2] = t.y; dv[4] = t.z; dv[6] = t.w;
    }
  }
  __syncthreads();

  const float* up_base = u_s + nl * kUSnl;
  const int mm = ((nl >> 2) & 1) * 8 + ((nl >> 1) & 1) * 4 + (nl & 1) * 2;
  const int kk = mm >> 2, j0 = mm & 3;

  for (int ch = 0; ch < kNCH; ch++) {
    const int bc  = ch * kCB;
    const int bc2 = ch * 4;  // b-pair base
    const int bca = bb0 + bc;

    // ---- u_ji tile, computed ONCE, held across barriers ----
    u64 acc[4][4];
    compute_acc(acc, up_base + bc, w, bp);

    if (MODE) {
      // agreement logits (v pair-packed from smem)
      u64 ag[4] = {0ull, 0ull, 0ull, 0ull};
#pragma unroll
      for (int k = 0; k < 4; k++) {
        const float* vp = v_s + (bc2 + k) * kVSbp + o * kVSo + eg * 8;
        ulonglong2 va = *(const ulonglong2*)vp;
        ulonglong2 vb = *(const ulonglong2*)(vp + 4);
        FMA2(ag[k], acc[k][0], va.x);
        FMA2(ag[k], acc[k][1], va.y);
        FMA2(ag[k], acc[k][2], vb.x);
        FMA2(ag[k], acc[k][3], vb.y);
      }
      // eg-reduction (lane bits 3,4), packed u64
#pragma unroll
      for (int k = 0; k < 4; k++) {
        u64 r = __shfl_xor_sync(0xffffffffu, ag[k], 8);
        ADD2(ag[k], ag[k], r);
        r = __shfl_xor_sync(0xffffffffu, ag[k], 16);
        ADD2(ag[k], ag[k], r);
      }
      if (eg == 0) {
        float* ar = l_s + nl * kLSnl + bc2 * kLSbp + o * 2;
#pragma unroll
        for (int k = 0; k < 4; k++)
          *(u64*)(ar + k * kLSbp) = ag[k];
      }
      __syncthreads();

      // pair-softmax for THIS chunk's 32 pair-rows (threads 0-31)
      if (tid < 32) {
        float* row = l_s + (tid >> 2) * kLSnl + (bc2 + (tid & 3)) * kLSbp;
        float ax[kO], ay[kO];
        float sx = 0.f, sy = 0.f;
#pragma unroll
        for (int q = 0; q < kO; q++) {
          float2 t = *(const float2*)(row + q * 2);
          ax[q] = __expf(t.x); ay[q] = __expf(t.y);
          sx += ax[q]; sy += ay[q];
        }
        float ix = 1.f / sx, iy = 1.f / sy;
#pragma unroll
        for (int q = 0; q < kO; q++)
          *(float2*)(row + q * 2) = make_float2(ax[q] * ix, ay[q] * iy);
      }
      __syncthreads();
    }

    // ---- weight by c (acc reused, no recompute) ----
    u64 v16[16];
    if (MODE) {
      const float* cp = l_s + nl * kLSnl + bc2 * kLSbp + o * 2;
#pragma unroll
      for (int k = 0; k < 4; k++) {
        u64 c2 = *(const u64*)(cp + k * kLSbp);
#pragma unroll
        for (int j = 0; j < 4; j++) MUL2(v16[k * 4 + j], acc[k][j], c2);
      }
    } else {
#pragma unroll
      for (int k = 0; k < 4; k++)
#pragma unroll
        for (int j = 0; j < 4; j++) v16[k * 4 + j] = acc[k][j];
    }

    // reduce-scatter over nl (lane bits 0-2)
    u64 v8[8];
    {
      const bool sel = (nl >> 2) & 1;
#pragma unroll
      for (int i = 0; i < 8; i++) {
        u64 send = sel ? v16[i] : v16[8 + i];
        u64 recv = __shfl_xor_sync(0xffffffffu, send, 4);
        u64 keep = sel ? v16[8 + i] : v16[i];
        ADD2(v8[i], keep, recv);
      }
    }
    u64 v4[4];
    {
      const bool sel = (nl >> 1) & 1;
#pragma unroll
      for (int i = 0; i < 4; i++) {
        u64 send = sel ? v8[i] : v8[4 + i];
        u64 recv = __shfl_xor_sync(0xffffffffu, send, 2);
        u64 keep = sel ? v8[4 + i] : v8[i];
        ADD2(v4[i], keep, recv);
      }
    }
    u64 v2[2];
    {
      const bool sel = nl & 1;
#pragma unroll
      for (int i = 0; i < 2; i++) {
        u64 send = sel ? v4[i] : v4[2 + i];
        u64 recv = __shfl_xor_sync(0xffffffffu, send, 1);
        u64 keep = sel ? v4[2 + i] : v4[i];
        ADD2(v2[i], keep, recv);
      }
    }
    {
      float l0, h0, l1, h1;
      UNPK2(l0, h0, v2[0]); UNPK2(l1, h1, v2[1]);
      float* dp = &g_part[((size_t)blockIdx.x * kB + bca + 2 * kk) * kOE
                          + o * kE + eg * 4 + j0];
      *(float2*)dp         = make_float2(l0, l1);
      *(float2*)(dp + kOE) = make_float2(h0, h1);
    }
  }
}

// Reduce 144 partials (p-loop split 4-way over lanes) + squash.
__global__ void squash_kernel(float* __restrict__ out, int mode, float scale) {
  int gt = blockIdx.x * blockDim.x + threadIdx.x;
  if (gt >= kB * kO * 4 * 4) return;            // 40960
  int h = gt & 3, eq = (gt >> 2) & 3, row = gt >> 4;  // row = b*10 + o
  const float* pp = g_part + (size_t)row * kE + eq * 4
                  + (size_t)(h * 36) * kB * kOE;
  float4 a = {0.f, 0.f, 0.f, 0.f};
#pragma unroll 4
  for (int p = 0; p < 36; p++) {
    float4 t = *(const float4*)(pp + (size_t)p * kB * kOE);
    a.x += t.x; a.y += t.y; a.z += t.z; a.w += t.w;
  }
  // combine p-quarters (lane bits 0,1)
  a.x += __shfl_xor_sync(0xffffffffu, a.x, 1);
  a.y += __shfl_xor_sync(0xffffffffu, a.y, 1);
  a.z += __shfl_xor_sync(0xffffffffu, a.z, 1);
  a.w += __shfl_xor_sync(0xffffffffu, a.w, 1);
  a.x += __shfl_xor_sync(0xffffffffu, a.x, 2);
  a.y += __shfl_xor_sync(0xffffffffu, a.y, 2);
  a.z += __shfl_xor_sync(0xffffffffu, a.z, 2);
  a.w += __shfl_xor_sync(0xffffffffu, a.w, 2);
  a.x *= scale; a.y *= scale; a.z *= scale; a.w *= scale;
  float n2 = a.x * a.x + a.y * a.y + a.z * a.z + a.w * a.w;
  n2 += __shfl_xor_sync(0xffffffffu, n2, 4);
  n2 += __shfl_xor_sync(0xffffffffu, n2, 8);
  float f = sqrtf(n2) / (1.f + n2);
  float4 v = make_float4(a.x * f, a.y * f, a.z * f, a.w * f);
  if (h == 0) {
    if (mode == 2) {
      *(float4*)(out + (size_t)row * kE + eq * 4) = v;
    } else if (mode == 1) {
      float4 old = *(const float4*)(g_vsum + (size_t)row * kE + eq * 4);
      v.x += old.x; v.y += old.y; v.z += old.z; v.w += old.w;
      *(float4*)(g_vsum + (size_t)row * kE + eq * 4) = v;
    } else {
      *(float4*)(g_vsum + (size_t)row * kE + eq * 4) = v;
    }
  }
}

extern "C" void kernel_launch(void* const* d_in, const int* in_sizes, int n_in,
                              void* d_out, int out_size) {
  const float* u    = (const float*)d_in[0];
  const float* W    = (const float*)d_in[1];
  const float* bias = (const float*)d_in[2];
  float* out = (float*)d_out;

  cudaFuncSetAttribute((const void*)pass_kernel<0>,
                       cudaFuncAttributeMaxDynamicSharedMemorySize, kSmemBytes0);
  cudaFuncSetAttribute((const void*)pass_kernel<1>,
                       cudaFuncAttributeMaxDynamicSharedMemorySize, kSmemBytes1);

  dim3 grid(kGX, kGY);  // 576 blocks, 2 CTAs/SM

  noop_kernel<<<1, 32>>>();  // keeps ncu -s 5 -c 1 on the 2nd pass_kernel<1>

  pass_kernel<0><<<grid, kTH, kSmemBytes0>>>(u, W, bias);
  squash_kernel<<<160, 256>>>(nullptr, 0, 0.1f);

  pass_kernel<1><<<grid, kTH, kSmemBytes1>>>(u, W, bias);
  squash_kernel<<<160, 256>>>(nullptr, 1, 1.0f);

  pass_kernel<1><<<grid, kTH, kSmemBytes1>>>(u, W, bias);
  squash_kernel<<<160, 256>>>(out, 2, 1.0f);
}